// round 1
// baseline (speedup 1.0000x reference)
#include <cuda_runtime.h>
#include <cstdint>

#define NIMG 8
#define NCLS 80
#define HW 40000
#define LOCS_PER_CHUNK 500
#define CHUNKS_PER_IMG (HW / LOCS_PER_CHUNK)   /* 80 */
#define F4_PER_ROW (LOCS_PER_CHUNK / 4)        /* 125 */
#define F4_PER_BLOCK (NCLS * F4_PER_ROW)       /* 10000 */
#define CAND_CAP 131072
#define TOPK 1000
#define OUTK 100

// ---------------- scratch (device globals; no allocation allowed) ----------
__device__ uint32_t            g_hist[NIMG][256];
__device__ int                 g_bc[NIMG];
__device__ int                 g_cnt[NIMG];
__device__ unsigned long long  g_cand[NIMG][CAND_CAP];
__device__ float               g_score[NIMG][TOPK];
__device__ int                 g_label[NIMG][TOPK];
__device__ float4              g_box[NIMG][TOPK];
__device__ float4              g_obox[NIMG][TOPK];

// XLA logistic expansion: 1 / (1 + exp(-x)), IEEE div (matches logistic_expander)
__device__ __forceinline__ float sigm(float x) {
    return __fdiv_rn(1.0f, __fadd_rn(1.0f, expf(-x)));
}

// ---------------------------------------------------------------------------
__global__ void k_zero() {
    int t = blockIdx.x * blockDim.x + threadIdx.x;
    if (t < NIMG * 256) ((uint32_t*)g_hist)[t] = 0;
    if (t < NIMG) g_cnt[t] = 0;
}

// ---------------------------------------------------------------------------
// K1: coarse histogram of candidate score keys (float bits >> 22)
__global__ void k_hist(const float* __restrict__ cls, const float* __restrict__ cent) {
    __shared__ float    s_cent[LOCS_PER_CHUNK];
    __shared__ uint32_t s_hist[256];
    const int n = blockIdx.y, chunk = blockIdx.x, tid = threadIdx.x;
    const int locBase = chunk * LOCS_PER_CHUNK;

    for (int i = tid; i < 256; i += blockDim.x) s_hist[i] = 0;
    for (int i = tid; i < LOCS_PER_CHUNK; i += blockDim.x)
        s_cent[i] = sigm(cent[n * HW + locBase + i]);
    __syncthreads();

    const float4* cls4 = (const float4*)cls;
    const long long imgBase = (long long)n * NCLS * (HW / 4) + (locBase / 4);

    const int iters = (F4_PER_BLOCK + 255) / 256;
    for (int it = 0; it < iters; ++it) {
        int e = it * 256 + tid;
        bool in = e < F4_PER_BLOCK;
        float4 v = make_float4(0.f, 0.f, 0.f, 0.f);
        int c = 0, wi = 0;
        if (in) {
            c = e / F4_PER_ROW; wi = e % F4_PER_ROW;
            v = cls4[imgBase + (long long)c * (HW / 4) + wi];
        }
        float xs[4] = {v.x, v.y, v.z, v.w};
        #pragma unroll
        for (int k = 0; k < 4; ++k) {
            bool cand = false;
            unsigned bin = 0;
            if (in) {
                float p = sigm(xs[k]);
                cand = p > 0.05f;
                if (cand) {
                    float sc = __fmul_rn(p, s_cent[wi * 4 + k]);
                    bin = __float_as_uint(sc) >> 22;
                }
            }
            unsigned m = __ballot_sync(0xffffffffu, cand);
            if (cand) {
                unsigned peers = __match_any_sync(m, bin);
                int leader = __ffs(peers) - 1;
                if ((tid & 31) == leader) atomicAdd(&s_hist[bin], (uint32_t)__popc(peers));
            }
        }
    }
    __syncthreads();
    for (int i = tid; i < 256; i += blockDim.x) {
        uint32_t val = s_hist[i];
        if (val) atomicAdd(&g_hist[n][i], val);
    }
}

// ---------------------------------------------------------------------------
// K2: find coarse cutoff bin per image (rank-1000 boundary)
__global__ void k_cutoff() {
    int n = threadIdx.x;
    if (n < NIMG) {
        int cum = 0, bc = 0;
        for (int b = 255; b >= 0; --b) {
            cum += (int)g_hist[n][b];
            if (cum >= TOPK) { bc = b; break; }
        }
        g_bc[n] = bc;
    }
}

// ---------------------------------------------------------------------------
// K3: collect (key, ~idx) for candidates at/above coarse cutoff
__global__ void k_collect(const float* __restrict__ cls, const float* __restrict__ cent) {
    __shared__ float s_cent[LOCS_PER_CHUNK];
    const int n = blockIdx.y, chunk = blockIdx.x, tid = threadIdx.x;
    const int locBase = chunk * LOCS_PER_CHUNK;
    const unsigned bc = (unsigned)g_bc[n];

    for (int i = tid; i < LOCS_PER_CHUNK; i += blockDim.x)
        s_cent[i] = sigm(cent[n * HW + locBase + i]);
    __syncthreads();

    const float4* cls4 = (const float4*)cls;
    const long long imgBase = (long long)n * NCLS * (HW / 4) + (locBase / 4);
    const int lane = tid & 31;

    const int iters = (F4_PER_BLOCK + 255) / 256;
    for (int it = 0; it < iters; ++it) {
        int e = it * 256 + tid;
        bool in = e < F4_PER_BLOCK;
        float4 v = make_float4(0.f, 0.f, 0.f, 0.f);
        int c = 0, wi = 0;
        if (in) {
            c = e / F4_PER_ROW; wi = e % F4_PER_ROW;
            v = cls4[imgBase + (long long)c * (HW / 4) + wi];
        }
        float xs[4] = {v.x, v.y, v.z, v.w};
        #pragma unroll
        for (int k = 0; k < 4; ++k) {
            bool sel = false;
            unsigned key = 0; unsigned idx = 0;
            if (in) {
                float p = sigm(xs[k]);
                if (p > 0.05f) {
                    float sc = __fmul_rn(p, s_cent[wi * 4 + k]);
                    key = __float_as_uint(sc);
                    if ((key >> 22) >= bc) {
                        sel = true;
                        int loc = locBase + wi * 4 + k;
                        idx = (unsigned)(loc * NCLS + c);
                    }
                }
            }
            unsigned m = __ballot_sync(0xffffffffu, sel);
            if (sel) {
                int leader = __ffs(m) - 1;
                int rank = __popc(m & ((1u << lane) - 1u));
                int base = 0;
                if (lane == leader) base = atomicAdd(&g_cnt[n], __popc(m));
                base = __shfl_sync(m, base, leader);
                int pos = base + rank;
                if (pos < CAND_CAP) {
                    g_cand[n][pos] = ((unsigned long long)key << 32) | (unsigned)(~idx);
                }
            }
        }
    }
}

// ---------------------------------------------------------------------------
// K4: exact top-1000 per image (fine hist -> refine -> bitonic sort), decode boxes
__global__ void __launch_bounds__(1024) k_select(const float* __restrict__ loc2,
                                                 const float* __restrict__ reg,
                                                 const int* __restrict__ isz) {
    __shared__ uint32_t s_hist[1024];
    __shared__ uint32_t s_cum[1024];
    __shared__ unsigned long long s_buf[4096];
    __shared__ int s_cnt2, s_bf;
    const int n = blockIdx.x, tid = threadIdx.x;
    const int Mn = min(g_cnt[n], CAND_CAP);
    const unsigned relbase = ((unsigned)g_bc[n]) << 6;

    s_hist[tid] = 0;
    if (tid == 0) { s_cnt2 = 0; s_bf = 0; }
    __syncthreads();

    for (int i = tid; i < Mn; i += 1024) {
        unsigned key = (unsigned)(g_cand[n][i] >> 32);
        unsigned rel = (key >> 16) - relbase;
        atomicAdd(&s_hist[min(rel, 1023u)], 1u);
    }
    __syncthreads();

    // inclusive suffix scan (Hillis-Steele)
    s_cum[tid] = s_hist[tid];
    __syncthreads();
    for (int off = 1; off < 1024; off <<= 1) {
        uint32_t add = (tid + off < 1024) ? s_cum[tid + off] : 0u;
        __syncthreads();
        s_cum[tid] += add;
        __syncthreads();
    }

    const int target = min(TOPK, Mn);
    if (Mn > 0) {
        if ((int)s_cum[tid] >= target && (tid == 1023 || (int)s_cum[tid + 1] < target))
            s_bf = tid;
    }
    __syncthreads();
    const unsigned bf = (unsigned)s_bf;

    for (int i = tid; i < Mn; i += 1024) {
        unsigned long long pk = g_cand[n][i];
        unsigned key = (unsigned)(pk >> 32);
        unsigned rel = min((key >> 16) - relbase, 1023u);
        if (rel >= bf) {
            int p = atomicAdd(&s_cnt2, 1);
            if (p < 4096) s_buf[p] = pk;
        }
    }
    __syncthreads();
    const int cnt2 = min(s_cnt2, 4096);
    for (int i = tid; i < 4096; i += 1024)
        if (i >= cnt2) s_buf[i] = 0ull;
    __syncthreads();

    // bitonic sort, descending (key desc, then ~idx desc == idx asc)
    for (int k = 2; k <= 4096; k <<= 1) {
        for (int j = k >> 1; j > 0; j >>= 1) {
            for (int t = tid; t < 4096; t += 1024) {
                int ixj = t ^ j;
                if (ixj > t) {
                    unsigned long long a = s_buf[t], b = s_buf[ixj];
                    bool up = (t & k) == 0;
                    if (up ? (a < b) : (a > b)) { s_buf[t] = b; s_buf[ixj] = a; }
                }
            }
            __syncthreads();
        }
    }

    if (tid < TOPK) {
        unsigned long long pk = (tid < cnt2) ? s_buf[tid] : 0ull;
        unsigned key = (unsigned)(pk >> 32);
        if (key == 0u) {
            g_score[n][tid] = 0.0f;
            g_label[n][tid] = 0;
            g_box[n][tid]  = make_float4(0.f, 0.f, 0.f, 0.f);
            g_obox[n][tid] = make_float4(0.f, 0.f, 0.f, 0.f);
        } else {
            unsigned idx = ~(unsigned)(pk & 0xffffffffull);
            int l = (int)(idx / NCLS), c = (int)(idx % NCLS);
            float sc = __uint_as_float(key);
            float lx = loc2[2 * l], ly = loc2[2 * l + 1];
            const float* rg = reg + (long long)n * 4 * HW;
            float r0 = rg[l], r1 = rg[HW + l], r2 = rg[2 * HW + l], r3 = rg[3 * HW + l];
            float ym = __fsub_rn((float)isz[2 * n],     1.0f);
            float xm = __fsub_rn((float)isz[2 * n + 1], 1.0f);
            float x1 = fminf(fmaxf(__fsub_rn(lx, r0), 0.0f), xm);
            float y1 = fminf(fmaxf(__fsub_rn(ly, r1), 0.0f), ym);
            float x2 = fminf(fmaxf(__fadd_rn(lx, r2), 0.0f), xm);
            float y2 = fminf(fmaxf(__fadd_rn(ly, r3), 0.0f), ym);
            int label = c + 1;
            float off = __fmul_rn((float)label, 100000.0f);  // exact product
            g_score[n][tid] = sc;
            g_label[n][tid] = label;
            g_box[n][tid]  = make_float4(x1, y1, x2, y2);
            g_obox[n][tid] = make_float4(__fadd_rn(x1, off), __fadd_rn(y1, off),
                                         __fadd_rn(x2, off), __fadd_rn(y2, off));
        }
    }
}

// ---------------------------------------------------------------------------
// K5: per-class greedy NMS (warp per class; cross-class IoU == 0 by offsets),
//     keep prefix-scan, top-100 output
__global__ void __launch_bounds__(1024) k_nms_out(float* __restrict__ out) {
    __shared__ float4         s_ob[TOPK];
    __shared__ float          s_area[TOPK];
    __shared__ unsigned char  s_lab[TOPK];
    __shared__ unsigned char  s_supp[TOPK];
    __shared__ unsigned short s_pool[TOPK];
    __shared__ int            s_count[NCLS];
    __shared__ int            s_off[NCLS + 1];
    __shared__ int            s_scan[1024];

    const int n = blockIdx.x, tid = threadIdx.x, lane = tid & 31, w = tid >> 5;

    if (tid < NCLS) s_count[tid] = 0;
    if (tid < TOPK) {
        float4 b = g_obox[n][tid];
        s_ob[tid] = b;
        // area = (x2-x1+1)*(y2-y1+1) on OFFSET boxes (matches reference bit-wise)
        s_area[tid] = __fmul_rn(__fadd_rn(__fsub_rn(b.z, b.x), 1.0f),
                                __fadd_rn(__fsub_rn(b.w, b.y), 1.0f));
        int L = g_label[n][tid];
        s_lab[tid] = (unsigned char)L;
        s_supp[tid] = 0;
        if (L > 0) atomicAdd(&s_count[L - 1], 1);
    }
    __syncthreads();
    if (tid == 0) {
        int a = 0;
        for (int c = 0; c < NCLS; ++c) { s_off[c] = a; a += s_count[c]; }
        s_off[NCLS] = a;
    }
    __syncthreads();

    // stable per-class gather (rank order preserved), warp w owns classes w, w+32, w+64
    for (int c = w; c < NCLS; c += 32) {
        int off = s_off[c], cnt = 0;
        unsigned char want = (unsigned char)(c + 1);
        for (int base = 0; base < TOPK; base += 32) {
            int r = base + lane;
            bool hit = (r < TOPK) && (s_lab[r] == want);
            unsigned m = __ballot_sync(0xffffffffu, hit);
            if (hit) s_pool[off + cnt + __popc(m & ((1u << lane) - 1u))] = (unsigned short)r;
            cnt += __popc(m);
        }
    }
    __syncthreads();

    // greedy NMS within each class
    for (int c = w; c < NCLS; c += 32) {
        int off = s_off[c], m = s_count[c];
        for (int i = 0; i < m; ++i) {
            __syncwarp();
            int ri = s_pool[off + i];
            if (s_supp[ri]) continue;
            float4 bi = s_ob[ri];
            float  ai = s_area[ri];
            for (int j = i + 1 + lane; j < m; j += 32) {
                int rj = s_pool[off + j];
                float4 bj = s_ob[rj];
                float ww = __fadd_rn(__fsub_rn(fminf(bi.z, bj.z), fmaxf(bi.x, bj.x)), 1.0f);
                float hh = __fadd_rn(__fsub_rn(fminf(bi.w, bj.w), fmaxf(bi.y, bj.y)), 1.0f);
                ww = fmaxf(ww, 0.0f); hh = fmaxf(hh, 0.0f);
                float inter = __fmul_rn(ww, hh);
                float uni = __fsub_rn(__fadd_rn(ai, s_area[rj]), inter);
                float iou = __fdiv_rn(inter, uni);
                if (iou > 0.6f) s_supp[rj] = 1;
            }
        }
        __syncwarp();
    }
    __syncthreads();

    int keep = (tid < TOPK && s_lab[tid] > 0 && !s_supp[tid]) ? 1 : 0;
    s_scan[tid] = keep;
    __syncthreads();
    for (int off = 1; off < 1024; off <<= 1) {
        int v = (tid >= off) ? s_scan[tid - off] : 0;
        __syncthreads();
        s_scan[tid] += v;
        __syncthreads();
    }

    for (int i = tid; i < OUTK * 6; i += 1024) out[n * OUTK * 6 + i] = 0.0f;
    __syncthreads();

    if (keep) {
        int pos = s_scan[tid] - 1;
        if (pos < OUTK) {
            float4 b = g_box[n][tid];
            float* o = out + n * OUTK * 6 + pos * 6;
            o[0] = b.x; o[1] = b.y; o[2] = b.z; o[3] = b.w;
            o[4] = sqrtf(g_score[n][tid]);
            o[5] = (float)g_label[n][tid];
        }
    }
}

// ---------------------------------------------------------------------------
extern "C" void kernel_launch(void* const* d_in, const int* in_sizes, int n_in,
                              void* d_out, int out_size) {
    const float* locations = (const float*)d_in[0];
    const float* box_cls   = (const float*)d_in[1];
    const float* box_reg   = (const float*)d_in[2];
    const float* cent      = (const float*)d_in[3];
    const int*   isz       = (const int*)d_in[4];
    float* out = (float*)d_out;

    k_zero<<<NIMG, 256>>>();
    dim3 g1(CHUNKS_PER_IMG, NIMG);
    k_hist<<<g1, 256>>>(box_cls, cent);
    k_cutoff<<<1, 32>>>();
    k_collect<<<g1, 256>>>(box_cls, cent);
    k_select<<<NIMG, 1024>>>(locations, box_reg, isz);
    k_nms_out<<<NIMG, 1024>>>(out);
}

// round 2
// speedup vs baseline: 1.4404x; 1.4404x over previous
#include <cuda_runtime.h>
#include <cstdint>

#define NIMG 8
#define NCLS 80
#define HW 40000
#define CAND_CAP 262144
#define TOPK 1000
#define OUTK 100
#define LINES_PP 1250            /* 128B lines per class plane (40000/32) */
#define LINES_PAD 1280
#define TAGS_PER_IMG (NCLS * LINES_PAD)   /* 102400 */

#define XC_TAG  (-2.9446f)       /* conservative superset of p>0.05 */
#define XC_HIST (-2.9443f)       /* conservative subset of p>0.05  */
#define CBIN    (-4.76837158203125e-7f)   /* -4 * 2^-23 */
#define BIN_MARGIN 5

// ---------------- scratch (device globals; no allocation allowed) ----------
__device__ uint32_t            g_hist[NIMG][256];
__device__ int                 g_bcm[NIMG];
__device__ int                 g_cnt[NIMG];
__device__ unsigned char       g_tag[NIMG * TAGS_PER_IMG];
__device__ unsigned long long  g_cand[NIMG][CAND_CAP];
__device__ float               g_score[NIMG][TOPK];
__device__ int                 g_label[NIMG][TOPK];
__device__ float4              g_box[NIMG][TOPK];
__device__ float4              g_obox[NIMG][TOPK];

// exact sigmoid: XLA logistic expansion 1/(1+exp(-x)), IEEE div
__device__ __forceinline__ float sigm(float x) {
    return __fdiv_rn(1.0f, __fadd_rn(1.0f, expf(-x)));
}

// cheap scaled softplus-log: returns ~ 2^23 * log2(1 + e^-v). No MUFU, no div.
// Used ONLY for approximate binning; identical function in pass1 and pass2.
__device__ __forceinline__ float slog(float v) {
    float u  = v * -1.4426950408889634f;                 // -v*log2(e)
    u = fmaxf(u, -126.0f);
    float fi = fmaf(u, 8388608.0f, 1065353216.0f);       // Schraudolph 2^u
    float ex = __int_as_float((int)fi);                  // ~= e^-v
    float w  = __fadd_rn(1.0f, ex);
    return (float)(__float_as_int(w) - 1065353216);      // ~= 2^23*log2(w)
}
// bin value: 256 + 4*log2(score_approx); element qualifies at bin >= bcm
__device__ __forceinline__ float bval(float sx, float sy) {
    return fmaf(sx + sy, CBIN, 256.0f);
}

// ---------------------------------------------------------------------------
__global__ void k_zero() {
    int t = blockIdx.x * blockDim.x + threadIdx.x;
    if (t < NIMG * 256) ((uint32_t*)g_hist)[t] = 0;
    if (t < NIMG) g_cnt[t] = 0;
}

// ---------------------------------------------------------------------------
// Pass 1: one full read of cls. Cheap approx bin per element; per-128B-line
// max bin -> 1-byte tag; line-level histogram for the cutoff.
__global__ void k_pass1(const float* __restrict__ cls, const float* __restrict__ cent) {
    __shared__ float    s_g[1024];
    __shared__ uint32_t s_hist[256];
    const int n = blockIdx.y, blk = blockIdx.x, tid = threadIdx.x;
    const int base = blk << 10;                 // w-range start (1024 per block)
    const int lim = min(1024, HW - base);

    for (int i = tid; i < 256; i += 256) s_hist[i] = 0;
    for (int i = tid; i < lim; i += 256)
        s_g[i] = slog(cent[n * HW + base + i]);
    __syncthreads();

    const float4* cls4 = (const float4*)cls;
    const int pf4 = (base >> 2) + tid;          // float4 index within plane
    const bool act = pf4 < (HW / 4);
    const int gline = (blk << 5) + (tid >> 3);  // global 32-elem line in plane
    const bool lvalid = gline < LINES_PP;
    const int tagbase = n * TAGS_PER_IMG + gline;
    const int ibase = n * (NCLS * (HW / 4)) + pf4;

    float g0 = 0.f, g1 = 0.f, g2 = 0.f, g3 = 0.f;
    if (act) { g0 = s_g[tid*4]; g1 = s_g[tid*4+1]; g2 = s_g[tid*4+2]; g3 = s_g[tid*4+3]; }

    for (int c = 0; c < NCLS; ++c) {
        float tmax = -1e30f, hmax = -1e30f;
        if (act) {
            float4 v = cls4[ibase + c * (HW / 4)];
            float b0 = bval(slog(v.x), g0);
            float b1 = bval(slog(v.y), g1);
            float b2 = bval(slog(v.z), g2);
            float b3 = bval(slog(v.w), g3);
            if (v.x > XC_TAG)  tmax = fmaxf(tmax, b0);
            if (v.y > XC_TAG)  tmax = fmaxf(tmax, b1);
            if (v.z > XC_TAG)  tmax = fmaxf(tmax, b2);
            if (v.w > XC_TAG)  tmax = fmaxf(tmax, b3);
            if (v.x > XC_HIST) hmax = fmaxf(hmax, b0);
            if (v.y > XC_HIST) hmax = fmaxf(hmax, b1);
            if (v.z > XC_HIST) hmax = fmaxf(hmax, b2);
            if (v.w > XC_HIST) hmax = fmaxf(hmax, b3);
        }
        tmax = fmaxf(tmax, __shfl_xor_sync(0xffffffffu, tmax, 1));
        tmax = fmaxf(tmax, __shfl_xor_sync(0xffffffffu, tmax, 2));
        tmax = fmaxf(tmax, __shfl_xor_sync(0xffffffffu, tmax, 4));
        hmax = fmaxf(hmax, __shfl_xor_sync(0xffffffffu, hmax, 1));
        hmax = fmaxf(hmax, __shfl_xor_sync(0xffffffffu, hmax, 2));
        hmax = fmaxf(hmax, __shfl_xor_sync(0xffffffffu, hmax, 4));
        if ((tid & 7) == 0 && lvalid) {
            int tb = (int)floorf(tmax);
            tb = max(0, min(255, tb));
            g_tag[tagbase + c * LINES_PAD] = (unsigned char)tb;
            if (hmax > -1e29f) {
                int hb = max(0, min(255, (int)floorf(hmax)));
                atomicAdd(&s_hist[hb], 1u);
            }
        }
    }
    __syncthreads();
    for (int i = tid; i < 256; i += 256) {
        uint32_t v = s_hist[i];
        if (v) atomicAdd(&g_hist[n][i], v);
    }
}

// ---------------------------------------------------------------------------
// cutoff: highest bin with >=1000 lines above, minus safety margin (approx err)
__global__ void k_cutoff() {
    int n = threadIdx.x;
    if (n >= NIMG) return;
    int cum[256];
    int acc = 0;
    for (int b = 255; b >= 0; --b) { acc += (int)g_hist[n][b]; cum[b] = acc; }
    int bcl = 0;
    for (int b = 255; b >= 0; --b) if (cum[b] >= TOPK) { bcl = b; break; }
    int m = bcl - BIN_MARGIN; if (m < 0) m = 0;
    while (m < bcl && 32 * cum[m] > CAND_CAP) ++m;   // capacity guard
    g_bcm[n] = m;
}

// ---------------------------------------------------------------------------
// Pass 2: tag-guided sparse collection. Only lines with tag >= bcm are read;
// exact sigmoid only for the few thousand surviving elements.
__global__ void k_collect2(const float* __restrict__ cls, const float* __restrict__ cent) {
    __shared__ int s_hits[1024];
    __shared__ int s_nhit;
    const int n = blockIdx.y, tid = threadIdx.x;
    const int slot0 = blockIdx.x * 1024;
    const int bcm = g_bcm[n];
    if (tid == 0) s_nhit = 0;
    __syncthreads();

    const unsigned char* tags = &g_tag[n * TAGS_PER_IMG];
    for (int i = tid; i < 1024; i += 256) {
        int slot = slot0 + i;
        int l32 = slot % LINES_PAD;
        if (l32 < LINES_PP && (int)tags[slot] >= bcm) {
            int p = atomicAdd(&s_nhit, 1);
            s_hits[p] = slot;
        }
    }
    __syncthreads();
    const int nh = s_nhit;
    const int w = tid >> 5, lane = tid & 31;
    const float fb = (float)bcm;

    for (int h = w; h < nh; h += 8) {
        int slot = s_hits[h];
        int c = slot / LINES_PAD, l32 = slot % LINES_PAD;
        int wpos = l32 * 32 + lane;
        float x = cls[(n * NCLS + c) * HW + wpos];
        float y = cent[n * HW + wpos];
        bool sel = false;
        unsigned key = 0, idx = 0;
        if (x > XC_TAG) {
            float b = bval(slog(x), slog(y));      // bit-identical to pass1
            if (b >= fb) {
                float p = sigm(x);                 // exact path for survivors
                if (p > 0.05f) {
                    float sc = __fmul_rn(p, sigm(y));
                    key = __float_as_uint(sc);
                    idx = (unsigned)(wpos * NCLS + c);
                    sel = true;
                }
            }
        }
        unsigned m = __ballot_sync(0xffffffffu, sel);
        if (sel) {
            int leader = __ffs(m) - 1;
            int rank = __popc(m & ((1u << lane) - 1u));
            int basep = 0;
            if (lane == leader) basep = atomicAdd(&g_cnt[n], __popc(m));
            basep = __shfl_sync(m, basep, leader);
            int pos = basep + rank;
            if (pos < CAND_CAP)
                g_cand[n][pos] = ((unsigned long long)key << 32) | (unsigned)(~idx);
        }
    }
}

// ---------------------------------------------------------------------------
// K4: exact top-1000 per image (maxkey-based fine hist -> refine -> bitonic),
// decode boxes
__global__ void __launch_bounds__(1024) k_select(const float* __restrict__ loc2,
                                                 const float* __restrict__ reg,
                                                 const int* __restrict__ isz) {
    __shared__ uint32_t s_hist[1024];
    __shared__ uint32_t s_cum[1024];
    __shared__ unsigned long long s_buf[4096];
    __shared__ unsigned s_wmax[32];
    __shared__ int s_cnt2, s_bf, s_rb;
    const int n = blockIdx.x, tid = threadIdx.x;
    const int Mn = min(g_cnt[n], CAND_CAP);

    s_hist[tid] = 0;
    if (tid == 0) { s_cnt2 = 0; s_bf = 0; }

    // max key
    unsigned mk = 0;
    for (int i = tid; i < Mn; i += 1024) mk = max(mk, (unsigned)(g_cand[n][i] >> 32));
    for (int o = 16; o; o >>= 1) mk = max(mk, __shfl_xor_sync(0xffffffffu, mk, o));
    if ((tid & 31) == 0) s_wmax[tid >> 5] = mk;
    __syncthreads();
    if (tid == 0) {
        unsigned m2 = 0;
        for (int i = 0; i < 32; ++i) m2 = max(m2, s_wmax[i]);
        s_rb = (int)(m2 >> 17) - 1023;
    }
    __syncthreads();
    const int relbase = s_rb;

    for (int i = tid; i < Mn; i += 1024) {
        unsigned key = (unsigned)(g_cand[n][i] >> 32);
        int rel = (int)(key >> 17) - relbase;
        if (rel >= 0) atomicAdd(&s_hist[rel], 1u);
    }
    __syncthreads();

    // inclusive suffix scan
    s_cum[tid] = s_hist[tid];
    __syncthreads();
    for (int off = 1; off < 1024; off <<= 1) {
        uint32_t add = (tid + off < 1024) ? s_cum[tid + off] : 0u;
        __syncthreads();
        s_cum[tid] += add;
        __syncthreads();
    }
    const int total = (int)s_cum[0];
    const int target = min(TOPK, total);
    if (target > 0) {
        if ((int)s_cum[tid] >= target && (tid == 1023 || (int)s_cum[tid + 1] < target))
            s_bf = tid;
    }
    __syncthreads();
    const int bf = s_bf;

    for (int i = tid; i < Mn; i += 1024) {
        unsigned long long pk = g_cand[n][i];
        int rel = (int)((unsigned)(pk >> 32) >> 17) - relbase;
        if (rel >= bf) {
            int p = atomicAdd(&s_cnt2, 1);
            if (p < 4096) s_buf[p] = pk;
        }
    }
    __syncthreads();
    const int cnt2 = min(s_cnt2, 4096);
    const int N2 = (cnt2 <= 2048) ? 2048 : 4096;
    for (int i = tid; i < N2; i += 1024)
        if (i >= cnt2) s_buf[i] = 0ull;
    __syncthreads();

    // bitonic sort, descending (key desc, then ~idx desc == idx asc)
    for (int k = 2; k <= N2; k <<= 1) {
        for (int j = k >> 1; j > 0; j >>= 1) {
            for (int t = tid; t < N2; t += 1024) {
                int ixj = t ^ j;
                if (ixj > t) {
                    unsigned long long a = s_buf[t], b = s_buf[ixj];
                    bool up = (t & k) == 0;
                    if (up ? (a < b) : (a > b)) { s_buf[t] = b; s_buf[ixj] = a; }
                }
            }
            __syncthreads();
        }
    }

    if (tid < TOPK) {
        unsigned long long pk = (tid < cnt2) ? s_buf[tid] : 0ull;
        unsigned key = (unsigned)(pk >> 32);
        if (key == 0u) {
            g_score[n][tid] = 0.0f;
            g_label[n][tid] = 0;
            g_box[n][tid]  = make_float4(0.f, 0.f, 0.f, 0.f);
            g_obox[n][tid] = make_float4(0.f, 0.f, 0.f, 0.f);
        } else {
            unsigned idx = ~(unsigned)(pk & 0xffffffffull);
            int l = (int)(idx / NCLS), c = (int)(idx % NCLS);
            float sc = __uint_as_float(key);
            float lx = loc2[2 * l], ly = loc2[2 * l + 1];
            const float* rg = reg + (long long)n * 4 * HW;
            float r0 = rg[l], r1 = rg[HW + l], r2 = rg[2 * HW + l], r3 = rg[3 * HW + l];
            float ym = __fsub_rn((float)isz[2 * n],     1.0f);
            float xm = __fsub_rn((float)isz[2 * n + 1], 1.0f);
            float x1 = fminf(fmaxf(__fsub_rn(lx, r0), 0.0f), xm);
            float y1 = fminf(fmaxf(__fsub_rn(ly, r1), 0.0f), ym);
            float x2 = fminf(fmaxf(__fadd_rn(lx, r2), 0.0f), xm);
            float y2 = fminf(fmaxf(__fadd_rn(ly, r3), 0.0f), ym);
            int label = c + 1;
            float off = __fmul_rn((float)label, 100000.0f);
            g_score[n][tid] = sc;
            g_label[n][tid] = label;
            g_box[n][tid]  = make_float4(x1, y1, x2, y2);
            g_obox[n][tid] = make_float4(__fadd_rn(x1, off), __fadd_rn(y1, off),
                                         __fadd_rn(x2, off), __fadd_rn(y2, off));
        }
    }
}

// ---------------------------------------------------------------------------
// K5: per-class greedy NMS (warp per class; cross-class IoU == 0 by offsets),
//     keep prefix-scan, top-100 output
__global__ void __launch_bounds__(1024) k_nms_out(float* __restrict__ out) {
    __shared__ float4         s_ob[TOPK];
    __shared__ float          s_area[TOPK];
    __shared__ unsigned char  s_lab[TOPK];
    __shared__ unsigned char  s_supp[TOPK];
    __shared__ unsigned short s_pool[TOPK];
    __shared__ int            s_count[NCLS];
    __shared__ int            s_off[NCLS + 1];
    __shared__ int            s_scan[1024];

    const int n = blockIdx.x, tid = threadIdx.x, lane = tid & 31, w = tid >> 5;

    if (tid < NCLS) s_count[tid] = 0;
    if (tid < TOPK) {
        float4 b = g_obox[n][tid];
        s_ob[tid] = b;
        s_area[tid] = __fmul_rn(__fadd_rn(__fsub_rn(b.z, b.x), 1.0f),
                                __fadd_rn(__fsub_rn(b.w, b.y), 1.0f));
        int L = g_label[n][tid];
        s_lab[tid] = (unsigned char)L;
        s_supp[tid] = 0;
        if (L > 0) atomicAdd(&s_count[L - 1], 1);
    }
    __syncthreads();
    if (tid == 0) {
        int a = 0;
        for (int c = 0; c < NCLS; ++c) { s_off[c] = a; a += s_count[c]; }
        s_off[NCLS] = a;
    }
    __syncthreads();

    for (int c = w; c < NCLS; c += 32) {
        int off = s_off[c], cnt = 0;
        unsigned char want = (unsigned char)(c + 1);
        for (int base = 0; base < TOPK; base += 32) {
            int r = base + lane;
            bool hit = (r < TOPK) && (s_lab[r] == want);
            unsigned m = __ballot_sync(0xffffffffu, hit);
            if (hit) s_pool[off + cnt + __popc(m & ((1u << lane) - 1u))] = (unsigned short)r;
            cnt += __popc(m);
        }
    }
    __syncthreads();

    for (int c = w; c < NCLS; c += 32) {
        int off = s_off[c], m = s_count[c];
        for (int i = 0; i < m; ++i) {
            __syncwarp();
            int ri = s_pool[off + i];
            if (s_supp[ri]) continue;
            float4 bi = s_ob[ri];
            float  ai = s_area[ri];
            for (int j = i + 1 + lane; j < m; j += 32) {
                int rj = s_pool[off + j];
                float4 bj = s_ob[rj];
                float ww = __fadd_rn(__fsub_rn(fminf(bi.z, bj.z), fmaxf(bi.x, bj.x)), 1.0f);
                float hh = __fadd_rn(__fsub_rn(fminf(bi.w, bj.w), fmaxf(bi.y, bj.y)), 1.0f);
                ww = fmaxf(ww, 0.0f); hh = fmaxf(hh, 0.0f);
                float inter = __fmul_rn(ww, hh);
                float uni = __fsub_rn(__fadd_rn(ai, s_area[rj]), inter);
                float iou = __fdiv_rn(inter, uni);
                if (iou > 0.6f) s_supp[rj] = 1;
            }
        }
        __syncwarp();
    }
    __syncthreads();

    int keep = (tid < TOPK && s_lab[tid] > 0 && !s_supp[tid]) ? 1 : 0;
    s_scan[tid] = keep;
    __syncthreads();
    for (int off = 1; off < 1024; off <<= 1) {
        int v = (tid >= off) ? s_scan[tid - off] : 0;
        __syncthreads();
        s_scan[tid] += v;
        __syncthreads();
    }

    for (int i = tid; i < OUTK * 6; i += 1024) out[n * OUTK * 6 + i] = 0.0f;
    __syncthreads();

    if (keep) {
        int pos = s_scan[tid] - 1;
        if (pos < OUTK) {
            float4 b = g_box[n][tid];
            float* o = out + n * OUTK * 6 + pos * 6;
            o[0] = b.x; o[1] = b.y; o[2] = b.z; o[3] = b.w;
            o[4] = sqrtf(g_score[n][tid]);
            o[5] = (float)g_label[n][tid];
        }
    }
}

// ---------------------------------------------------------------------------
extern "C" void kernel_launch(void* const* d_in, const int* in_sizes, int n_in,
                              void* d_out, int out_size) {
    const float* locations = (const float*)d_in[0];
    const float* box_cls   = (const float*)d_in[1];
    const float* box_reg   = (const float*)d_in[2];
    const float* cent      = (const float*)d_in[3];
    const int*   isz       = (const int*)d_in[4];
    float* out = (float*)d_out;

    k_zero<<<NIMG, 256>>>();
    k_pass1<<<dim3(40, NIMG), 256>>>(box_cls, cent);
    k_cutoff<<<1, 32>>>();
    k_collect2<<<dim3(100, NIMG), 256>>>(box_cls, cent);
    k_select<<<NIMG, 1024>>>(locations, box_reg, isz);
    k_nms_out<<<NIMG, 1024>>>(out);
}